// round 16
// baseline (speedup 1.0000x reference)
#include <cuda_runtime.h>
#include <cuda_bf16.h>
#include <math.h>
#include <cstdint>

// Problem constants
#define BB 128
#define NN 64
#define DD 768
#define HH 32
#define DK 24
#define LL 4
#define TE 32
#define TD 40
#define VP 512

// ---------------- scratch (device globals; no allocations allowed) -------------
__device__ float g_pb[BB*HH*NN*NN];        // path bias [b,h,i,j]
__device__ unsigned short g_cd[BB*NN*NN];  // packed conn | dist<<8
__device__ uint32_t g_q32p[BB*HH*NN*28];   // q tf32, padded [b,h,n,28]
__device__ uint32_t g_k32p[BB*HH*NN*28];   // k tf32, padded
__device__ uint32_t g_v32t[BB*HH*DK*NN];   // v tf32, transposed [b,h,d,n]
__device__ uint32_t g_btq32[HH*80*28];     // per-head BTQ (Ek|Dk), pads zeroed
__device__ uint32_t g_btk32[HH*80*28];     // per-head BTK (Eq|Dq)
__device__ uint32_t g_vtab32[HH*24*72];    // per-head (Ev|Dv) in VT column order
__device__ uint32_t g_a32[8192*768];       // node_reps as tf32
__device__ uint32_t g_wq32[2304*768];      // W_qkv transposed [n][k], tf32
__device__ uint32_t g_wo32[768*768];       // W_out transposed [n][k], tf32
__device__ uint32_t g_z32[8192*768];       // z as tf32, [b*n][h*dk]

// ---------------- tf32 helpers ---------------------------------------------------
__device__ __forceinline__ uint32_t f2tf32(float f) {
    uint32_t r;
    asm("cvt.rna.tf32.f32 %0, %1;" : "=r"(r) : "f"(f));
    return r;
}

__device__ __forceinline__ void mma_tf32(float* d, const uint32_t* a, const uint32_t* b) {
    asm volatile("mma.sync.aligned.m16n8k8.row.col.f32.tf32.tf32.f32 "
        "{%0,%1,%2,%3}, {%4,%5,%6,%7}, {%8,%9}, {%0,%1,%2,%3};"
        : "+f"(d[0]), "+f"(d[1]), "+f"(d[2]), "+f"(d[3])
        : "r"(a[0]), "r"(a[1]), "r"(a[2]), "r"(a[3]), "r"(b[0]), "r"(b[1]));
}

__device__ __forceinline__ void cp16(uint32_t saddr, const void* g) {
    asm volatile("cp.async.ca.shared.global [%0], [%1], 16;" :: "r"(saddr), "l"(g));
}

// ---------------- merged prepass: conv A + pack cd + pack tables ----------------
__global__ void __launch_bounds__(256) prepass_kernel(const float* __restrict__ X,
                                                      const int* __restrict__ conn,
                                                      const int* __restrict__ distv,
                                                      const float* __restrict__ Eq,
                                                      const float* __restrict__ Ek,
                                                      const float* __restrict__ Dq,
                                                      const float* __restrict__ Dk,
                                                      const float* __restrict__ Ev,
                                                      const float* __restrict__ Dv) {
    int bid = blockIdx.x, tid = threadIdx.x;
    if (bid < 6144) {
        int idx = (bid * 256 + tid) * 4;
        float4 v = *(const float4*)(X + idx);
        uint4 o = { f2tf32(v.x), f2tf32(v.y), f2tf32(v.z), f2tf32(v.w) };
        *(uint4*)(g_a32 + idx) = o;
    } else if (bid < 6144 + 2048) {
        int idx = (bid - 6144) * 256 + tid;
        g_cd[idx] = (unsigned short)(conn[idx] | (distv[idx] << 8));
    } else {
        int h = bid - 8192;
        for (int e = tid; e < 80 * 28; e += 256) {
            int t = e / 28, d = e - t * 28;
            uint32_t v1 = 0, v2 = 0;
            if (d < 24) {
                if (t < 32)      { v1 = f2tf32(Ek[(t * HH + h) * DK + d]);        v2 = f2tf32(Eq[(t * HH + h) * DK + d]); }
                else if (t < 72) { v1 = f2tf32(Dk[((t - 32) * HH + h) * DK + d]); v2 = f2tf32(Dq[((t - 32) * HH + h) * DK + d]); }
            }
            g_btq32[h * 2240 + e] = v1;
            g_btk32[h * 2240 + e] = v2;
        }
        for (int e = tid; e < 24 * 72; e += 256) {
            int d = e / 72, t = e - d * 72;
            uint32_t v = (t < 32) ? f2tf32(Ev[(t * HH + h) * DK + d])
                                  : f2tf32(Dv[((t - 32) * HH + h) * DK + d]);
            g_vtab32[h * 1728 + e] = v;
        }
    }
}

template<int NLD>
__global__ void convT_kernel(const float* __restrict__ W, uint32_t* __restrict__ Wt) {
    __shared__ float t[32][33];
    int k0 = blockIdx.y * 32, n0 = blockIdx.x * 32;
    int x = threadIdx.x, y = threadIdx.y;  // 32x8
    for (int yy = y; yy < 32; yy += 8)
        t[yy][x] = W[(k0 + yy) * NLD + n0 + x];
    __syncthreads();
    for (int yy = y; yy < 32; yy += 8)
        Wt[(n0 + yy) * 768 + k0 + x] = f2tf32(t[x][yy]);
}

// ---------------- 2-stage pipelined GEMM, 4 warps, 64x64 warp tile --------------
// CTA 128x128, 128 threads (2x2 warp grid). Halves smem fragment traffic vs 8-warp.
template<bool QKV>
__global__ void __launch_bounds__(128, 2) mma_gemm_kernel(const uint32_t* __restrict__ A,
                                                          const uint32_t* __restrict__ Bt,
                                                          const float* __restrict__ bias,
                                                          float* __restrict__ Cout) {
    extern __shared__ uint32_t sm[];
    uint32_t* Abuf = sm;                 // [2][128*36]
    uint32_t* Bbuf = sm + 2 * 128 * 36;  // [2][128*36]
    int tid = threadIdx.x;
    int wid = tid >> 5, lane = tid & 31;
    int group = lane >> 2, four = lane & 3;
    int wm = (wid >> 1) * 64, wn = (wid & 1) * 64;
    int m0 = blockIdx.y * 128, c0 = blockIdx.x * 128;

    uint32_t sbase;
    { uint64_t a = __cvta_generic_to_shared(sm); sbase = (uint32_t)a; }

    int ldrow = tid;                      // one thread per row
    const uint32_t* Arow = A + (m0 + ldrow) * 768;
    const uint32_t* Brow = Bt + (c0 + ldrow) * 768;
    uint32_t sArow = sbase + (ldrow * 36) * 4;
    uint32_t sBrow = sbase + (2 * 128 * 36 + ldrow * 36) * 4;

    #pragma unroll
    for (int c = 0; c < 8; c++) {
        cp16(sArow + c * 16, Arow + c * 4);
        cp16(sBrow + c * 16, Brow + c * 4);
    }
    asm volatile("cp.async.commit_group;");

    float acc[4][8][4] = {};
    #pragma unroll 1
    for (int s = 0; s < 24; s++) {
        int buf = s & 1;
        if (s + 1 < 24) {
            int nb = (s + 1) & 1;
            uint32_t soA = sArow + nb * (128 * 36 * 4);
            uint32_t soB = sBrow + nb * (128 * 36 * 4);
            const uint32_t* gA = Arow + (s + 1) * 32;
            const uint32_t* gB = Brow + (s + 1) * 32;
            #pragma unroll
            for (int c = 0; c < 8; c++) {
                cp16(soA + c * 16, gA + c * 4);
                cp16(soB + c * 16, gB + c * 4);
            }
            asm volatile("cp.async.commit_group;");
            asm volatile("cp.async.wait_group 1;");
        } else {
            asm volatile("cp.async.wait_group 0;");
        }
        __syncthreads();
        const uint32_t* As = Abuf + buf * (128 * 36);
        const uint32_t* Bs = Bbuf + buf * (128 * 36);
        #pragma unroll
        for (int ks = 0; ks < 4; ks++) {
            int kk = ks * 8;
            uint32_t af[4][4], bf[8][2];
            #pragma unroll
            for (int fm = 0; fm < 4; fm++) {
                int r = wm + fm * 16 + group;
                af[fm][0] = As[r * 36 + kk + four];
                af[fm][1] = As[(r + 8) * 36 + kk + four];
                af[fm][2] = As[r * 36 + kk + four + 4];
                af[fm][3] = As[(r + 8) * 36 + kk + four + 4];
            }
            #pragma unroll
            for (int fn = 0; fn < 8; fn++) {
                int n = wn + fn * 8 + group;
                bf[fn][0] = Bs[n * 36 + kk + four];
                bf[fn][1] = Bs[n * 36 + kk + four + 4];
            }
            #pragma unroll
            for (int fm = 0; fm < 4; fm++)
                #pragma unroll
                for (int fn = 0; fn < 8; fn++)
                    mma_tf32(acc[fm][fn], af[fm], bf[fn]);
        }
        __syncthreads();
    }
    // epilogue: paired STG.64; QKV path stores attn-ready tf32 layouts
    #pragma unroll
    for (int fm = 0; fm < 4; fm++) {
        #pragma unroll
        for (int fn = 0; fn < 8; fn++) {
            #pragma unroll
            for (int hf = 0; hf < 2; hf++) {
                int m = m0 + wm + fm * 16 + group + hf * 8;
                int c = c0 + wn + fn * 8 + four * 2;
                float vx = acc[fm][fn][hf * 2 + 0] + bias[c];
                float vy = acc[fm][fn][hf * 2 + 1] + bias[c + 1];
                if (QKV) {
                    int b = m >> 6, n = m & 63;
                    int sx = c / 768, rem = c - sx * 768;
                    int hh = rem / 24, d = rem % 24;
                    uint2 o = { f2tf32(vx), f2tf32(vy) };
                    if (sx == 0)      *(uint2*)&g_q32p[((b * HH + hh) * NN + n) * 28 + d] = o;
                    else if (sx == 1) *(uint2*)&g_k32p[((b * HH + hh) * NN + n) * 28 + d] = o;
                    else {
                        g_v32t[((b * HH + hh) * DK + d) * NN + n]     = o.x;
                        g_v32t[((b * HH + hh) * DK + d + 1) * NN + n] = o.y;
                    }
                } else {
                    float2 v2 = { vx, vy };
                    *(float2*)&Cout[m * 768 + c] = v2;
                }
            }
        }
    }
}

// ---------------- Kernel B: path bias (MLP-hoisted loads, 4-row staging) --------
__global__ void __launch_bounds__(256) path_kernel(const int* __restrict__ traj,
                                                   const int* __restrict__ distv,
                                                   const float* __restrict__ pemb,
                                                   const float* __restrict__ ppw) {
    extern __shared__ float ps[];
    float* pe = ps;                  // 512*32
    float* stage = ps + VP * HH;     // 4 * 64*33
    int b = blockIdx.x >> 1;
    int i0 = (blockIdx.x & 1) * 32;
    int tid = threadIdx.x;
    for (int e = tid; e < VP * HH; e += 256) pe[e] = pemb[e];
    int w = tid >> 5, lane = tid & 31;
    float w0 = ppw[lane], w1 = ppw[32 + lane], w2 = ppw[64 + lane], w3 = ppw[96 + lane];
    __syncthreads();
    for (int ib = 0; ib < 8; ib++) {
        #pragma unroll
        for (int r = 0; r < 4; r++) {
            int i = i0 + ib * 4 + r;
            int idxs[8];
            float dns[8];
            #pragma unroll
            for (int jj = 0; jj < 8; jj++) {
                int j = w * 8 + jj;
                idxs[jj] = (lane < 12) ? traj[(((b * NN + i) * NN) + j) * 12 + lane] : 0;
            }
            #pragma unroll
            for (int jj = 0; jj < 8; jj++)
                dns[jj] = fmaxf((float)distv[(b * NN + i) * NN + w * 8 + jj], 1.f);
            #pragma unroll
            for (int jj = 0; jj < 8; jj++) {
                float acc = 0.f;
                #pragma unroll
                for (int t = 0; t < 12; t++) {
                    int id = __shfl_sync(0xffffffffu, idxs[jj], t);
                    float wl = (t < 3) ? w0 : (t < 6) ? w1 : (t < 9) ? w2 : w3;
                    acc += pe[id * 32 + lane] * wl;
                }
                stage[r * 2112 + (w * 8 + jj) * 33 + lane] = acc / dns[jj];
            }
        }
        __syncthreads();
        for (int e = tid; e < HH * NN * 4; e += 256) {
            int r = e >> 11;
            int rem = e & 2047;
            int hh = rem >> 6, j = rem & 63;
            int i = i0 + ib * 4 + r;
            g_pb[(((b * HH + hh) * NN + i) << 6) + j] = stage[r * 2112 + j * 33 + hh];
        }
        __syncthreads();
    }
}

// ---------------- Kernel C: attention, fused glue, 2 CTAs/SM --------------------
#define QS 28
#define QBS 83
#define KBS 81
#define CW 137
#define OFF_Q    0
#define OFF_K    1792
#define OFF_BTQ  3584
#define OFF_BTK  5824
#define OFF_VT   3584          // overlay after phase 1/2
#define OFF_QB   8064          // 64*83 = 5312
#define OFF_KB   13376         // 64*81 = 5184
#define OFF_COMB 18560         // 64*137 = 8768
#define OFF_TR   27328
#define OFF_TC   27392
#define FWORDS   27456
#define BYT_MASK (FWORDS*4)
#define ATTN_SMEM_BYTES (BYT_MASK + 64)

__global__ void __launch_bounds__(256, 2) attn_kernel(const unsigned char* __restrict__ mask,
                                                   const float* __restrict__ Tr, const float* __restrict__ Tc) {
    extern __shared__ char sraw[];
    float* sf = (float*)sraw;
    uint32_t* su = (uint32_t*)sraw;
    unsigned char* mk = (unsigned char*)sraw + BYT_MASK;

    int h = blockIdx.x, b = blockIdx.y;
    int tid = threadIdx.x;
    int wid = tid >> 5, lane = tid & 31;
    int group = lane >> 2, four = lane & 3;
    int cdoff = b * NN * NN;
    int pboff = (b * HH + h) * NN * NN;

    // ---- early prefetch, softmax-aligned ----
    float pbv[8][2];
    unsigned short cdv[8][2];
    #pragma unroll
    for (int r = 0; r < 8; r++) {
        #pragma unroll
        for (int hf = 0; hf < 2; hf++) {
            int e = (wid * 8 + r) * 64 + hf * 32 + lane;
            pbv[r][hf] = g_pb[pboff + e];
            cdv[r][hf] = g_cd[cdoff + e];
        }
    }

    // ---- init: pure coalesced copies ----
    {
        const uint4* qsrc = (const uint4*)&g_q32p[(b * HH + h) * 1792];
        const uint4* ksrc = (const uint4*)&g_k32p[(b * HH + h) * 1792];
        uint4* qd = (uint4*)(su + OFF_Q);
        uint4* kd = (uint4*)(su + OFF_K);
        for (int e = tid; e < 448; e += 256) { qd[e] = qsrc[e]; kd[e] = ksrc[e]; }
        const uint4* bq = (const uint4*)&g_btq32[h * 2240];
        const uint4* bk = (const uint4*)&g_btk32[h * 2240];
        uint4* bqd = (uint4*)(su + OFF_BTQ);
        uint4* bkd = (uint4*)(su + OFF_BTK);
        for (int e = tid; e < 560; e += 256) { bqd[e] = bq[e]; bkd[e] = bk[e]; }
    }
    for (int e = tid; e < NN * 72; e += 256) {
        int i = e / 72, t = e - i * 72;
        sf[OFF_COMB + i * CW + 64 + t] = 0.f;
    }
    if (tid < NN) {
        mk[tid] = mask[b * NN + tid];
        sf[OFF_TR + tid] = Tr[h * NN + tid];
        sf[OFF_TC + tid] = Tc[h * NN + tid];
    }
    __syncthreads();

    // ---- phase 1 (mma): qb/kb [64 x 72 live cols], K=24 ----
    {
        int side = wid >> 2;
        int ws = wid & 3;
        const uint32_t* Am = su + (side ? OFF_K : OFF_Q);
        const uint32_t* Bm = su + (side ? OFF_BTK : OFF_BTQ);
        float* Dm = sf + (side ? OFF_KB : OFF_QB);
        int stride = side ? KBS : QBS;
        for (int chunk = ws; chunk < 9; chunk += 4) {
            int n0 = chunk * 8;
            float c[4][4] = {};
            #pragma unroll
            for (int ks = 0; ks < 3; ks++) {
                int kk = ks * 8;
                uint32_t bf[2] = { Bm[(n0 + group) * QS + kk + four],
                                   Bm[(n0 + group) * QS + kk + four + 4] };
                #pragma unroll
                for (int fm = 0; fm < 4; fm++) {
                    int r = fm * 16 + group;
                    uint32_t af[4] = { Am[r * QS + kk + four], Am[(r + 8) * QS + kk + four],
                                       Am[r * QS + kk + four + 4], Am[(r + 8) * QS + kk + four + 4] };
                    mma_tf32(c[fm], af, bf);
                }
            }
            #pragma unroll
            for (int fm = 0; fm < 4; fm++)
                #pragma unroll
                for (int r = 0; r < 4; r++)
                    Dm[(fm * 16 + group + ((r >> 1) ? 8 : 0)) * stride + n0 + four * 2 + (r & 1)] = c[fm][r];
        }
    }
    // ---- phase 2 (mma): raw scores q@k^T -> comb cols 0..63 ----
    {
        int wm = (wid >> 2) * 32, wn = (wid & 3) * 16;
        float c[2][2][4] = {};
        #pragma unroll
        for (int ks = 0; ks < 3; ks++) {
            int kk = ks * 8;
            uint32_t af[2][4], bf[2][2];
            #pragma unroll
            for (int fm = 0; fm < 2; fm++) {
                int r = wm + fm * 16 + group;
                af[fm][0] = su[OFF_Q + r * QS + kk + four];
                af[fm][1] = su[OFF_Q + (r + 8) * QS + kk + four];
                af[fm][2] = su[OFF_Q + r * QS + kk + four + 4];
                af[fm][3] = su[OFF_Q + (r + 8) * QS + kk + four + 4];
            }
            #pragma unroll
            for (int fn = 0; fn < 2; fn++) {
                int n = wn + fn * 8 + group;
                bf[fn][0] = su[OFF_K + n * QS + kk + four];
                bf[fn][1] = su[OFF_K + n * QS + kk + four + 4];
            }
            #pragma unroll
            for (int fm = 0; fm < 2; fm++)
                #pragma unroll
                for (int fn = 0; fn < 2; fn++)
                    mma_tf32(c[fm][fn], af[fm], bf[fn]);
        }
        #pragma unroll
        for (int fm = 0; fm < 2; fm++)
            #pragma unroll
            for (int fn = 0; fn < 2; fn++)
                #pragma unroll
                for (int r = 0; r < 4; r++) {
                    int i = wm + fm * 16 + group + ((r >> 1) ? 8 : 0);
                    int j = wn + fn * 8 + four * 2 + (r & 1);
                    sf[OFF_COMB + i * CW + j] = c[fm][fn][r];
                }
    }
    __syncthreads();

    // ---- overlay: VT fill + fused assembly/softmax/toeplitz/scatter ----
    for (int e = tid; e < 24 * 72; e += 256) {
        int d = e / 72, t = e - d * 72;
        su[OFF_VT + d * CW + 64 + t] = g_vtab32[h * 1728 + e];
    }
    for (int e = tid; e < NN * DK; e += 256) {
        su[OFF_VT + (e >> 6) * CW + (e & 63)] = g_v32t[(b * HH + h) * 1536 + e];
    }
    {
        const float scale = 0.2041241452319315f;  // 24^-0.5
        int j0 = lane, j1 = lane + 32;
        float tmask0 = mk[j0] ? 1.f : 0.f;
        float tmask1 = mk[j1] ? 1.f : 0.f;
        #pragma unroll
        for (int r = 0; r < 8; r++) {
            int i = wid * 8 + r;
            int c0v = cdv[r][0] & 0xff, d0v = cdv[r][0] >> 8;
            int c1v = cdv[r][1] & 0xff, d1v = cdv[r][1] >> 8;
            float a0 = sf[OFF_COMB + i * CW + j0]
                     + sf[OFF_QB + i * QBS + c0v] + sf[OFF_KB + j0 * KBS + c0v]
                     + sf[OFF_QB + i * QBS + 32 + d0v] + sf[OFF_KB + j0 * KBS + 32 + d0v]
                     + pbv[r][0];
            float a1 = sf[OFF_COMB + i * CW + j1]
                     + sf[OFF_QB + i * QBS + c1v] + sf[OFF_KB + j1 * KBS + c1v]
                     + sf[OFF_QB + i * QBS + 32 + d1v] + sf[OFF_KB + j1 * KBS + 32 + d1v]
                     + pbv[r][1];
            a0 = tmask0 != 0.f ? -1e30f : a0 * scale;
            a1 = tmask1 != 0.f ? -1e30f : a1 * scale;
            float m = fmaxf(a0, a1);
            #pragma unroll
            for (int o = 16; o; o >>= 1) m = fmaxf(m, __shfl_xor_sync(0xffffffffu, m, o));
            float e0 = __expf(a0 - m), e1 = __expf(a1 - m);
            float ssum = e0 + e1;
            #pragma unroll
            for (int o = 16; o; o >>= 1) ssum += __shfl_xor_sync(0xffffffffu, ssum, o);
            float inv = 1.f / ssum;
            float t0 = (j0 >= i) ? sf[OFF_TR + j0 - i] : sf[OFF_TC + i - j0];
            float t1 = (j1 >= i) ? sf[OFF_TR + j1 - i] : sf[OFF_TC + i - j1];
            float p0 = e0 * inv * t0;
            float p1 = e1 * inv * t1;
            su[OFF_COMB + i * CW + j0] = f2tf32(p0);
            su[OFF_COMB + i * CW + j1] = f2tf32(p1);
            atomicAdd(&sf[OFF_COMB + i * CW + 64 + c0v], p0);
            atomicAdd(&sf[OFF_COMB + i * CW + 96 + d0v], p0);
            atomicAdd(&sf[OFF_COMB + i * CW + 64 + c1v], p1);
            atomicAdd(&sf[OFF_COMB + i * CW + 96 + d1v], p1);
        }
    }
    __syncthreads();

    // ---- phase 5 (mma): z = comb[64x136] @ VT^T[136x24]; convert at read ----
    for (int p = wid; p < 12; p += 8) {
        int pm = (p & 3) * 16;
        int pn = (p >> 2) * 8;
        float c[4] = {};
        #pragma unroll
        for (int ks = 0; ks < 17; ks++) {
            int kk = ks * 8;
            uint32_t af[4] = { f2tf32(sf[OFF_COMB + (pm + group) * CW + kk + four]),
                               f2tf32(sf[OFF_COMB + (pm + group + 8) * CW + kk + four]),
                               f2tf32(sf[OFF_COMB + (pm + group) * CW + kk + four + 4]),
                               f2tf32(sf[OFF_COMB + (pm + group + 8) * CW + kk + four + 4]) };
            uint32_t bf[2] = { su[OFF_VT + (pn + group) * CW + kk + four],
                               su[OFF_VT + (pn + group) * CW + kk + four + 4] };
            mma_tf32(c, af, bf);
        }
        #pragma unroll
        for (int hf = 0; hf < 2; hf++) {
            int i = pm + group + hf * 8;
            int d = pn + four * 2;
            uint2 z2 = { f2tf32(c[hf * 2 + 0]), f2tf32(c[hf * 2 + 1]) };
            *(uint2*)&g_z32[(b * NN + i) * 768 + h * DK + d] = z2;
        }
    }
}

// ---------------- launch --------------------------------------------------------
extern "C" void kernel_launch(void* const* d_in, const int* in_sizes, int n_in,
                              void* d_out, int out_size) {
    const float* node   = (const float*)d_in[0];
    const int*   distv  = (const int*)d_in[1];
    const int*   conn   = (const int*)d_in[2];
    const int*   traj   = (const int*)d_in[3];
    const unsigned char* mask = (const unsigned char*)d_in[4];
    const float* W_qkv  = (const float*)d_in[5];
    const float* b_qkv  = (const float*)d_in[6];
    const float* W_out  = (const float*)d_in[7];
    const float* b_out  = (const float*)d_in[8];
    const float* Eq     = (const float*)d_in[9];
    const float* Ek     = (const float*)d_in[10];
    const float* Dq     = (const float*)d_in[11];
    const float* Dk     = (const float*)d_in[12];
    const float* pemb   = (const float*)d_in[13];
    const float* ppw    = (const float*)d_in[14];
    const float* Ev     = (const float*)d_in[15];
    const float* Dv     = (const float*)d_in[16];
    const float* Tr     = (const float*)d_in[17];
    const float* Tc     = (const float*)d_in[18];
    float* out = (float*)d_out;

    int attn_smem = ATTN_SMEM_BYTES;
    int path_smem = (VP * HH + 4 * 64 * 33) * (int)sizeof(float);
    int gemm_smem = 4 * 128 * 36 * 4;
    cudaFuncSetAttribute(attn_kernel, cudaFuncAttributeMaxDynamicSharedMemorySize, attn_smem);
    cudaFuncSetAttribute(path_kernel, cudaFuncAttributeMaxDynamicSharedMemorySize, path_smem);
    cudaFuncSetAttribute(mma_gemm_kernel<true>,  cudaFuncAttributeMaxDynamicSharedMemorySize, gemm_smem);
    cudaFuncSetAttribute(mma_gemm_kernel<false>, cudaFuncAttributeMaxDynamicSharedMemorySize, gemm_smem);

    uint32_t *wq32p, *wo32p, *a32p, *z32p;
    cudaGetSymbolAddress((void**)&wq32p, g_wq32);
    cudaGetSymbolAddress((void**)&wo32p, g_wo32);
    cudaGetSymbolAddress((void**)&a32p, g_a32);
    cudaGetSymbolAddress((void**)&z32p, g_z32);

    prepass_kernel<<<6144 + 2048 + 32, 256>>>(node, conn, distv, Eq, Ek, Dq, Dk, Ev, Dv);
    convT_kernel<2304><<<dim3(72, 24), dim3(32, 8)>>>(W_qkv, wq32p);
    convT_kernel<768><<<dim3(24, 24), dim3(32, 8)>>>(W_out, wo32p);

    mma_gemm_kernel<true><<<dim3(2304/128, 8192/128), 128, gemm_smem>>>(a32p, wq32p, b_qkv, nullptr);
    path_kernel<<<BB * 2, 256, path_smem>>>(traj, distv, pemb, ppw);
    attn_kernel<<<dim3(HH, BB), 256, attn_smem>>>(mask, Tr, Tc);
    mma_gemm_kernel<false><<<dim3(768/128, 8192/128), 128, gemm_smem>>>(z32p, wo32p, b_out, out);
}

// round 17
// speedup vs baseline: 1.1313x; 1.1313x over previous
#include <cuda_runtime.h>
#include <cuda_bf16.h>
#include <math.h>
#include <cstdint>

// Problem constants
#define BB 128
#define NN 64
#define DD 768
#define HH 32
#define DK 24
#define LL 4
#define TE 32
#define TD 40
#define VP 512

// ---------------- scratch (device globals; no allocations allowed) -------------
__device__ float g_pb[BB*HH*NN*NN];        // path bias [b,h,i,j]
__device__ unsigned short g_cd[BB*NN*NN];  // packed conn | dist<<8
__device__ uint32_t g_q32p[BB*HH*NN*28];   // q tf32, padded [b,h,n,28]
__device__ uint32_t g_k32p[BB*HH*NN*28];   // k tf32, padded
__device__ uint32_t g_v32t[BB*HH*DK*NN];   // v tf32, transposed [b,h,d,n]
__device__ uint32_t g_btq32[HH*80*28];     // per-head BTQ (Ek|Dk), pads zeroed
__device__ uint32_t g_btk32[HH*80*28];     // per-head BTK (Eq|Dq)
__device__ uint32_t g_vtab32[HH*24*72];    // per-head (Ev|Dv) in VT column order
__device__ uint32_t g_a32[8192*768];       // node_reps as tf32
__device__ uint32_t g_wq32[2304*768];      // W_qkv transposed [n][k], tf32
__device__ uint32_t g_wo32[768*768];       // W_out transposed [n][k], tf32
__device__ uint32_t g_z32[8192*768];       // z as tf32, [b*n][h*dk]

// ---------------- tf32 helpers ---------------------------------------------------
__device__ __forceinline__ uint32_t f2tf32(float f) {
    uint32_t r;
    asm("cvt.rna.tf32.f32 %0, %1;" : "=r"(r) : "f"(f));
    return r;
}

__device__ __forceinline__ void mma_tf32(float* d, const uint32_t* a, const uint32_t* b) {
    asm volatile("mma.sync.aligned.m16n8k8.row.col.f32.tf32.tf32.f32 "
        "{%0,%1,%2,%3}, {%4,%5,%6,%7}, {%8,%9}, {%0,%1,%2,%3};"
        : "+f"(d[0]), "+f"(d[1]), "+f"(d[2]), "+f"(d[3])
        : "r"(a[0]), "r"(a[1]), "r"(a[2]), "r"(a[3]), "r"(b[0]), "r"(b[1]));
}

__device__ __forceinline__ void cp16(uint32_t saddr, const void* g) {
    asm volatile("cp.async.ca.shared.global [%0], [%1], 16;" :: "r"(saddr), "l"(g));
}

// ---------------- merged prepass: conv A + pack cd + pack tables ----------------
__global__ void __launch_bounds__(256) prepass_kernel(const float* __restrict__ X,
                                                      const int* __restrict__ conn,
                                                      const int* __restrict__ distv,
                                                      const float* __restrict__ Eq,
                                                      const float* __restrict__ Ek,
                                                      const float* __restrict__ Dq,
                                                      const float* __restrict__ Dk,
                                                      const float* __restrict__ Ev,
                                                      const float* __restrict__ Dv) {
    int bid = blockIdx.x, tid = threadIdx.x;
    if (bid < 6144) {
        int idx = (bid * 256 + tid) * 4;
        float4 v = *(const float4*)(X + idx);
        uint4 o = { f2tf32(v.x), f2tf32(v.y), f2tf32(v.z), f2tf32(v.w) };
        *(uint4*)(g_a32 + idx) = o;
    } else if (bid < 6144 + 2048) {
        int idx = (bid - 6144) * 256 + tid;
        g_cd[idx] = (unsigned short)(conn[idx] | (distv[idx] << 8));
    } else {
        int h = bid - 8192;
        for (int e = tid; e < 80 * 28; e += 256) {
            int t = e / 28, d = e - t * 28;
            uint32_t v1 = 0, v2 = 0;
            if (d < 24) {
                if (t < 32)      { v1 = f2tf32(Ek[(t * HH + h) * DK + d]);        v2 = f2tf32(Eq[(t * HH + h) * DK + d]); }
                else if (t < 72) { v1 = f2tf32(Dk[((t - 32) * HH + h) * DK + d]); v2 = f2tf32(Dq[((t - 32) * HH + h) * DK + d]); }
            }
            g_btq32[h * 2240 + e] = v1;
            g_btk32[h * 2240 + e] = v2;
        }
        for (int e = tid; e < 24 * 72; e += 256) {
            int d = e / 72, t = e - d * 72;
            uint32_t v = (t < 32) ? f2tf32(Ev[(t * HH + h) * DK + d])
                                  : f2tf32(Dv[((t - 32) * HH + h) * DK + d]);
            g_vtab32[h * 1728 + e] = v;
        }
    }
}

template<int NLD>
__global__ void convT_kernel(const float* __restrict__ W, uint32_t* __restrict__ Wt) {
    __shared__ float t[32][33];
    int k0 = blockIdx.y * 32, n0 = blockIdx.x * 32;
    int x = threadIdx.x, y = threadIdx.y;  // 32x8
    for (int yy = y; yy < 32; yy += 8)
        t[yy][x] = W[(k0 + yy) * NLD + n0 + x];
    __syncthreads();
    for (int yy = y; yy < 32; yy += 8)
        Wt[(n0 + yy) * 768 + k0 + x] = f2tf32(t[x][yy]);
}

// ---------------- 2-stage pipelined GEMM (R14-verified: 8 warps, 64x32 tile) ----
template<bool QKV>
__global__ void __launch_bounds__(256, 2) mma_gemm_kernel(const uint32_t* __restrict__ A,
                                                          const uint32_t* __restrict__ Bt,
                                                          const float* __restrict__ bias,
                                                          float* __restrict__ Cout) {
    extern __shared__ uint32_t sm[];
    uint32_t* Abuf = sm;                 // [2][128*36]
    uint32_t* Bbuf = sm + 2 * 128 * 36;  // [2][128*36]
    int tid = threadIdx.x;
    int wid = tid >> 5, lane = tid & 31;
    int group = lane >> 2, four = lane & 3;
    int wm = (wid >> 2) * 64, wn = (wid & 3) * 32;
    int m0 = blockIdx.y * 128, c0 = blockIdx.x * 128;

    uint32_t sbase;
    { uint64_t a = __cvta_generic_to_shared(sm); sbase = (uint32_t)a; }

    int ldrow = tid >> 1;
    int ldch4 = (tid & 1) * 16;
    const uint32_t* Arow = A + (m0 + ldrow) * 768 + ldch4;
    const uint32_t* Brow = Bt + (c0 + ldrow) * 768 + ldch4;
    uint32_t sArow = sbase + (ldrow * 36 + ldch4) * 4;
    uint32_t sBrow = sbase + (2 * 128 * 36 + ldrow * 36 + ldch4) * 4;

    #pragma unroll
    for (int c = 0; c < 4; c++) {
        cp16(sArow + c * 16, Arow + c * 4);
        cp16(sBrow + c * 16, Brow + c * 4);
    }
    asm volatile("cp.async.commit_group;");

    float acc[4][4][4] = {};
    #pragma unroll 1
    for (int s = 0; s < 24; s++) {
        int buf = s & 1;
        if (s + 1 < 24) {
            int nb = (s + 1) & 1;
            uint32_t soA = sArow + nb * (128 * 36 * 4);
            uint32_t soB = sBrow + nb * (128 * 36 * 4);
            const uint32_t* gA = Arow + (s + 1) * 32;
            const uint32_t* gB = Brow + (s + 1) * 32;
            #pragma unroll
            for (int c = 0; c < 4; c++) {
                cp16(soA + c * 16, gA + c * 4);
                cp16(soB + c * 16, gB + c * 4);
            }
            asm volatile("cp.async.commit_group;");
            asm volatile("cp.async.wait_group 1;");
        } else {
            asm volatile("cp.async.wait_group 0;");
        }
        __syncthreads();
        const uint32_t* As = Abuf + buf * (128 * 36);
        const uint32_t* Bs = Bbuf + buf * (128 * 36);
        #pragma unroll
        for (int ks = 0; ks < 4; ks++) {
            int kk = ks * 8;
            uint32_t af[4][4], bf[4][2];
            #pragma unroll
            for (int fm = 0; fm < 4; fm++) {
                int r = wm + fm * 16 + group;
                af[fm][0] = As[r * 36 + kk + four];
                af[fm][1] = As[(r + 8) * 36 + kk + four];
                af[fm][2] = As[r * 36 + kk + four + 4];
                af[fm][3] = As[(r + 8) * 36 + kk + four + 4];
            }
            #pragma unroll
            for (int fn = 0; fn < 4; fn++) {
                int n = wn + fn * 8 + group;
                bf[fn][0] = Bs[n * 36 + kk + four];
                bf[fn][1] = Bs[n * 36 + kk + four + 4];
            }
            #pragma unroll
            for (int fm = 0; fm < 4; fm++)
                #pragma unroll
                for (int fn = 0; fn < 4; fn++)
                    mma_tf32(acc[fm][fn], af[fm], bf[fn]);
        }
        __syncthreads();
    }
    // epilogue: paired STG.64; QKV path stores attn-ready tf32 layouts
    #pragma unroll
    for (int fm = 0; fm < 4; fm++) {
        #pragma unroll
        for (int fn = 0; fn < 4; fn++) {
            #pragma unroll
            for (int hf = 0; hf < 2; hf++) {
                int m = m0 + wm + fm * 16 + group + hf * 8;
                int c = c0 + wn + fn * 8 + four * 2;
                float vx = acc[fm][fn][hf * 2 + 0] + bias[c];
                float vy = acc[fm][fn][hf * 2 + 1] + bias[c + 1];
                if (QKV) {
                    int b = m >> 6, n = m & 63;
                    int sx = c / 768, rem = c - sx * 768;
                    int hh = rem / 24, d = rem % 24;
                    uint2 o = { f2tf32(vx), f2tf32(vy) };
                    if (sx == 0)      *(uint2*)&g_q32p[((b * HH + hh) * NN + n) * 28 + d] = o;
                    else if (sx == 1) *(uint2*)&g_k32p[((b * HH + hh) * NN + n) * 28 + d] = o;
                    else {
                        g_v32t[((b * HH + hh) * DK + d) * NN + n]     = o.x;
                        g_v32t[((b * HH + hh) * DK + d + 1) * NN + n] = o.y;
                    }
                } else {
                    float2 v2 = { vx, vy };
                    *(float2*)&Cout[m * 768 + c] = v2;
                }
            }
        }
    }
}

// ---------------- Kernel B: path bias (MLP-hoisted loads, 4-row staging) --------
__global__ void __launch_bounds__(256) path_kernel(const int* __restrict__ traj,
                                                   const int* __restrict__ distv,
                                                   const float* __restrict__ pemb,
                                                   const float* __restrict__ ppw) {
    extern __shared__ float ps[];
    float* pe = ps;                  // 512*32
    float* stage = ps + VP * HH;     // 4 * 64*33
    int b = blockIdx.x >> 1;
    int i0 = (blockIdx.x & 1) * 32;
    int tid = threadIdx.x;
    for (int e = tid; e < VP * HH; e += 256) pe[e] = pemb[e];
    int w = tid >> 5, lane = tid & 31;
    float w0 = ppw[lane], w1 = ppw[32 + lane], w2 = ppw[64 + lane], w3 = ppw[96 + lane];
    __syncthreads();
    for (int ib = 0; ib < 8; ib++) {
        #pragma unroll
        for (int r = 0; r < 4; r++) {
            int i = i0 + ib * 4 + r;
            int idxs[8];
            float dns[8];
            #pragma unroll
            for (int jj = 0; jj < 8; jj++) {
                int j = w * 8 + jj;
                idxs[jj] = (lane < 12) ? traj[(((b * NN + i) * NN) + j) * 12 + lane] : 0;
            }
            #pragma unroll
            for (int jj = 0; jj < 8; jj++)
                dns[jj] = fmaxf((float)distv[(b * NN + i) * NN + w * 8 + jj], 1.f);
            #pragma unroll
            for (int jj = 0; jj < 8; jj++) {
                float acc = 0.f;
                #pragma unroll
                for (int t = 0; t < 12; t++) {
                    int id = __shfl_sync(0xffffffffu, idxs[jj], t);
                    float wl = (t < 3) ? w0 : (t < 6) ? w1 : (t < 9) ? w2 : w3;
                    acc += pe[id * 32 + lane] * wl;
                }
                stage[r * 2112 + (w * 8 + jj) * 33 + lane] = acc / dns[jj];
            }
        }
        __syncthreads();
        for (int e = tid; e < HH * NN * 4; e += 256) {
            int r = e >> 11;
            int rem = e & 2047;
            int hh = rem >> 6, j = rem & 63;
            int i = i0 + ib * 4 + r;
            g_pb[(((b * HH + hh) * NN + i) << 6) + j] = stage[r * 2112 + j * 33 + hh];
        }
        __syncthreads();
    }
}

// ---------------- Kernel C: attention, fused glue, 2 CTAs/SM --------------------
#define QS 28
#define QBS 83
#define KBS 81
#define CW 137
#define OFF_Q    0
#define OFF_K    1792
#define OFF_BTQ  3584
#define OFF_BTK  5824
#define OFF_VT   3584          // overlay after phase 1/2
#define OFF_QB   8064          // 64*83 = 5312
#define OFF_KB   13376         // 64*81 = 5184
#define OFF_COMB 18560         // 64*137 = 8768
#define OFF_TR   27328
#define OFF_TC   27392
#define FWORDS   27456
#define BYT_MASK (FWORDS*4)
#define ATTN_SMEM_BYTES (BYT_MASK + 64)

__global__ void __launch_bounds__(256, 2) attn_kernel(const unsigned char* __restrict__ mask,
                                                   const float* __restrict__ Tr, const float* __restrict__ Tc) {
    extern __shared__ char sraw[];
    float* sf = (float*)sraw;
    uint32_t* su = (uint32_t*)sraw;
    unsigned char* mk = (unsigned char*)sraw + BYT_MASK;

    int h = blockIdx.x, b = blockIdx.y;
    int tid = threadIdx.x;
    int wid = tid >> 5, lane = tid & 31;
    int group = lane >> 2, four = lane & 3;
    int cdoff = b * NN * NN;
    int pboff = (b * HH + h) * NN * NN;

    // ---- early prefetch, softmax-aligned ----
    float pbv[8][2];
    unsigned short cdv[8][2];
    #pragma unroll
    for (int r = 0; r < 8; r++) {
        #pragma unroll
        for (int hf = 0; hf < 2; hf++) {
            int e = (wid * 8 + r) * 64 + hf * 32 + lane;
            pbv[r][hf] = g_pb[pboff + e];
            cdv[r][hf] = g_cd[cdoff + e];
        }
    }

    // ---- init: pure coalesced copies ----
    {
        const uint4* qsrc = (const uint4*)&g_q32p[(b * HH + h) * 1792];
        const uint4* ksrc = (const uint4*)&g_k32p[(b * HH + h) * 1792];
        uint4* qd = (uint4*)(su + OFF_Q);
        uint4* kd = (uint4*)(su + OFF_K);
        for (int e = tid; e < 448; e += 256) { qd[e] = qsrc[e]; kd[e] = ksrc[e]; }
        const uint4* bq = (const uint4*)&g_btq32[h * 2240];
        const uint4* bk = (const uint4*)&g_btk32[h * 2240];
        uint4* bqd = (uint4*)(su + OFF_BTQ);
        uint4* bkd = (uint4*)(su + OFF_BTK);
        for (int e = tid; e < 560; e += 256) { bqd[e] = bq[e]; bkd[e] = bk[e]; }
    }
    for (int e = tid; e < NN * 72; e += 256) {
        int i = e / 72, t = e - i * 72;
        sf[OFF_COMB + i * CW + 64 + t] = 0.f;
    }
    if (tid < NN) {
        mk[tid] = mask[b * NN + tid];
        sf[OFF_TR + tid] = Tr[h * NN + tid];
        sf[OFF_TC + tid] = Tc[h * NN + tid];
    }
    __syncthreads();

    // ---- phase 1 (mma): qb/kb [64 x 72 live cols], K=24 ----
    {
        int side = wid >> 2;
        int ws = wid & 3;
        const uint32_t* Am = su + (side ? OFF_K : OFF_Q);
        const uint32_t* Bm = su + (side ? OFF_BTK : OFF_BTQ);
        float* Dm = sf + (side ? OFF_KB : OFF_QB);
        int stride = side ? KBS : QBS;
        for (int chunk = ws; chunk < 9; chunk += 4) {
            int n0 = chunk * 8;
            float c[4][4] = {};
            #pragma unroll
            for (int ks = 0; ks < 3; ks++) {
                int kk = ks * 8;
                uint32_t bf[2] = { Bm[(n0 + group) * QS + kk + four],
                                   Bm[(n0 + group) * QS + kk + four + 4] };
                #pragma unroll
                for (int fm = 0; fm < 4; fm++) {
                    int r = fm * 16 + group;
                    uint32_t af[4] = { Am[r * QS + kk + four], Am[(r + 8) * QS + kk + four],
                                       Am[r * QS + kk + four + 4], Am[(r + 8) * QS + kk + four + 4] };
                    mma_tf32(c[fm], af, bf);
                }
            }
            #pragma unroll
            for (int fm = 0; fm < 4; fm++)
                #pragma unroll
                for (int r = 0; r < 4; r++)
                    Dm[(fm * 16 + group + ((r >> 1) ? 8 : 0)) * stride + n0 + four * 2 + (r & 1)] = c[fm][r];
        }
    }
    // ---- phase 2 (mma): raw scores q@k^T -> comb cols 0..63 ----
    {
        int wm = (wid >> 2) * 32, wn = (wid & 3) * 16;
        float c[2][2][4] = {};
        #pragma unroll
        for (int ks = 0; ks < 3; ks++) {
            int kk = ks * 8;
            uint32_t af[2][4], bf[2][2];
            #pragma unroll
            for (int fm = 0; fm < 2; fm++) {
                int r = wm + fm * 16 + group;
                af[fm][0] = su[OFF_Q + r * QS + kk + four];
                af[fm][1] = su[OFF_Q + (r + 8) * QS + kk + four];
                af[fm][2] = su[OFF_Q + r * QS + kk + four + 4];
                af[fm][3] = su[OFF_Q + (r + 8) * QS + kk + four + 4];
            }
            #pragma unroll
            for (int fn = 0; fn < 2; fn++) {
                int n = wn + fn * 8 + group;
                bf[fn][0] = su[OFF_K + n * QS + kk + four];
                bf[fn][1] = su[OFF_K + n * QS + kk + four + 4];
            }
            #pragma unroll
            for (int fm = 0; fm < 2; fm++)
                #pragma unroll
                for (int fn = 0; fn < 2; fn++)
                    mma_tf32(c[fm][fn], af[fm], bf[fn]);
        }
        #pragma unroll
        for (int fm = 0; fm < 2; fm++)
            #pragma unroll
            for (int fn = 0; fn < 2; fn++)
                #pragma unroll
                for (int r = 0; r < 4; r++) {
                    int i = wm + fm * 16 + group + ((r >> 1) ? 8 : 0);
                    int j = wn + fn * 8 + four * 2 + (r & 1);
                    sf[OFF_COMB + i * CW + j] = c[fm][fn][r];
                }
    }
    __syncthreads();

    // ---- overlay: VT fill + fused assembly/softmax/toeplitz/scatter ----
    for (int e = tid; e < 24 * 72; e += 256) {
        int d = e / 72, t = e - d * 72;
        su[OFF_VT + d * CW + 64 + t] = g_vtab32[h * 1728 + e];
    }
    for (int e = tid; e < NN * DK; e += 256) {
        su[OFF_VT + (e >> 6) * CW + (e & 63)] = g_v32t[(b * HH + h) * 1536 + e];
    }
    {
        const float scale = 0.2041241452319315f;  // 24^-0.5
        int j0 = lane, j1 = lane + 32;
        float tmask0 = mk[j0] ? 1.f : 0.f;
        float tmask1 = mk[j1] ? 1.f : 0.f;
        #pragma unroll
        for (int r = 0; r < 8; r++) {
            int i = wid * 8 + r;
            int c0v = cdv[r][0] & 0xff, d0v = cdv[r][0] >> 8;
            int c1v = cdv[r][1] & 0xff, d1v = cdv[r][1] >> 8;
            float a0 = sf[OFF_COMB + i * CW + j0]
                     + sf[OFF_QB + i * QBS + c0v] + sf[OFF_KB + j0 * KBS + c0v]
                     + sf[OFF_QB + i * QBS + 32 + d0v] + sf[OFF_KB + j0 * KBS + 32 + d0v]
                     + pbv[r][0];
            float a1 = sf[OFF_COMB + i * CW + j1]
                     + sf[OFF_QB + i * QBS + c1v] + sf[OFF_KB + j1 * KBS + c1v]
                     + sf[OFF_QB + i * QBS + 32 + d1v] + sf[OFF_KB + j1 * KBS + 32 + d1v]
                     + pbv[r][1];
            a0 = tmask0 != 0.f ? -1e30f : a0 * scale;
            a1 = tmask1 != 0.f ? -1e30f : a1 * scale;
            float m = fmaxf(a0, a1);
            #pragma unroll
            for (int o = 16; o; o >>= 1) m = fmaxf(m, __shfl_xor_sync(0xffffffffu, m, o));
            float e0 = __expf(a0 - m), e1 = __expf(a1 - m);
            float ssum = e0 + e1;
            #pragma unroll
            for (int o = 16; o; o >>= 1) ssum += __shfl_xor_sync(0xffffffffu, ssum, o);
            float inv = 1.f / ssum;
            float t0 = (j0 >= i) ? sf[OFF_TR + j0 - i] : sf[OFF_TC + i - j0];
            float t1 = (j1 >= i) ? sf[OFF_TR + j1 - i] : sf[OFF_TC + i - j1];
            float p0 = e0 * inv * t0;
            float p1 = e1 * inv * t1;
            su[OFF_COMB + i * CW + j0] = f2tf32(p0);
            su[OFF_COMB + i * CW + j1] = f2tf32(p1);
            atomicAdd(&sf[OFF_COMB + i * CW + 64 + c0v], p0);
            atomicAdd(&sf[OFF_COMB + i * CW + 96 + d0v], p0);
            atomicAdd(&sf[OFF_COMB + i * CW + 64 + c1v], p1);
            atomicAdd(&sf[OFF_COMB + i * CW + 96 + d1v], p1);
        }
    }
    __syncthreads();

    // ---- phase 5 (mma): z = comb[64x136] @ VT^T[136x24]; dual accumulators ----
    for (int p = wid; p < 12; p += 8) {
        int pm = (p & 3) * 16;
        int pn = (p >> 2) * 8;
        float c[4] = {}, c2[4] = {};
        #pragma unroll
        for (int ks = 0; ks < 17; ks++) {
            int kk = ks * 8;
            uint32_t af[4] = { f2tf32(sf[OFF_COMB + (pm + group) * CW + kk + four]),
                               f2tf32(sf[OFF_COMB + (pm + group + 8) * CW + kk + four]),
                               f2tf32(sf[OFF_COMB + (pm + group) * CW + kk + four + 4]),
                               f2tf32(sf[OFF_COMB + (pm + group + 8) * CW + kk + four + 4]) };
            uint32_t bf[2] = { su[OFF_VT + (pn + group) * CW + kk + four],
                               su[OFF_VT + (pn + group) * CW + kk + four + 4] };
            if (ks & 1) mma_tf32(c2, af, bf);
            else        mma_tf32(c, af, bf);
        }
        #pragma unroll
        for (int r = 0; r < 4; r++) c[r] += c2[r];
        #pragma unroll
        for (int hf = 0; hf < 2; hf++) {
            int i = pm + group + hf * 8;
            int d = pn + four * 2;
            uint2 z2 = { f2tf32(c[hf * 2 + 0]), f2tf32(c[hf * 2 + 1]) };
            *(uint2*)&g_z32[(b * NN + i) * 768 + h * DK + d] = z2;
        }
    }
}

// ---------------- launch --------------------------------------------------------
extern "C" void kernel_launch(void* const* d_in, const int* in_sizes, int n_in,
                              void* d_out, int out_size) {
    const float* node   = (const float*)d_in[0];
    const int*   distv  = (const int*)d_in[1];
    const int*   conn   = (const int*)d_in[2];
    const int*   traj   = (const int*)d_in[3];
    const unsigned char* mask = (const unsigned char*)d_in[4];
    const float* W_qkv  = (const float*)d_in[5];
    const float* b_qkv  = (const float*)d_in[6];
    const float* W_out  = (const float*)d_in[7];
    const float* b_out  = (const float*)d_in[8];
    const float* Eq     = (const float*)d_in[9];
    const float* Ek     = (const float*)d_in[10];
    const float* Dq     = (const float*)d_in[11];
    const float* Dk     = (const float*)d_in[12];
    const float* pemb   = (const float*)d_in[13];
    const float* ppw    = (const float*)d_in[14];
    const float* Ev     = (const float*)d_in[15];
    const float* Dv     = (const float*)d_in[16];
    const float* Tr     = (const float*)d_in[17];
    const float* Tc     = (const float*)d_in[18];
    float* out = (float*)d_out;

    int attn_smem = ATTN_SMEM_BYTES;
    int path_smem = (VP * HH + 4 * 64 * 33) * (int)sizeof(float);
    int gemm_smem = 4 * 128 * 36 * 4;
    cudaFuncSetAttribute(attn_kernel, cudaFuncAttributeMaxDynamicSharedMemorySize, attn_smem);
    cudaFuncSetAttribute(path_kernel, cudaFuncAttributeMaxDynamicSharedMemorySize, path_smem);
    cudaFuncSetAttribute(mma_gemm_kernel<true>,  cudaFuncAttributeMaxDynamicSharedMemorySize, gemm_smem);
    cudaFuncSetAttribute(mma_gemm_kernel<false>, cudaFuncAttributeMaxDynamicSharedMemorySize, gemm_smem);

    uint32_t *wq32p, *wo32p, *a32p, *z32p;
    cudaGetSymbolAddress((void**)&wq32p, g_wq32);
    cudaGetSymbolAddress((void**)&wo32p, g_wo32);
    cudaGetSymbolAddress((void**)&a32p, g_a32);
    cudaGetSymbolAddress((void**)&z32p, g_z32);

    prepass_kernel<<<6144 + 2048 + 32, 256>>>(node, conn, distv, Eq, Ek, Dq, Dk, Ev, Dv);
    convT_kernel<2304><<<dim3(72, 24), dim3(32, 8)>>>(W_qkv, wq32p);
    convT_kernel<768><<<dim3(24, 24), dim3(32, 8)>>>(W_out, wo32p);

    mma_gemm_kernel<true><<<dim3(2304/128, 8192/128), 256, gemm_smem>>>(a32p, wq32p, b_qkv, nullptr);
    path_kernel<<<BB * 2, 256, path_smem>>>(traj, distv, pemb, ppw);
    attn_kernel<<<dim3(HH, BB), 256, attn_smem>>>(mask, Tr, Tc);
    mma_gemm_kernel<false><<<dim3(768/128, 8192/128), 256, gemm_smem>>>(z32p, wo32p, b_out, out);
}